// round 16
// baseline (speedup 1.0000x reference)
#include <cuda_runtime.h>

#define H 1024
#define B 8
#define T 4096
#define NROWS (B * T)

#define GRID      296              // 148 SMs x 2 blocks — all co-resident
#define NWARPS    (GRID * 8)       // 2368 warps, 13-14 rows each
#define V_WRITERS 256              // blocks 0..255 compute 4 v-rows each

__device__ float g_v[B * H];
__device__ int   g_cnt;            // writer blocks done (self-resetting)
__device__ int   g_passed;         // blocks past spin (self-resetting)

__device__ __forceinline__ int ld_acquire(const int* p) {
    int v;
    asm volatile("ld.global.acquire.gpu.b32 %0, [%1];" : "=r"(v) : "l"(p) : "memory");
    return v;
}

__device__ __forceinline__ void load_row(float4 (&x)[8],
                                         const float* __restrict__ states,
                                         int row, int lane)
{
    const float4* s4 = reinterpret_cast<const float4*>(states + (size_t)row * H);
#pragma unroll
    for (int k = 0; k < 8; k++) x[k] = s4[lane + 32 * k];
}

__device__ __forceinline__ void dot_store(const float4 (&x)[8],
                                          int row, int lane, float bb,
                                          float* __restrict__ out)
{
    const float4* v4 = reinterpret_cast<const float4*>(g_v + ((row >> 12) << 10));
    float acc0 = 0.0f, acc1 = 0.0f;
#pragma unroll
    for (int k = 0; k < 8; k += 2) {
        const float4 w0 = __ldg(v4 + lane + 32 * k);
        const float4 w1 = __ldg(v4 + lane + 32 * (k + 1));
        acc0 += x[k].x * w0.x + x[k].y * w0.y + x[k].z * w0.z + x[k].w * w0.w;
        acc1 += x[k+1].x * w1.x + x[k+1].y * w1.y + x[k+1].z * w1.z + x[k+1].w * w1.w;
    }
    float acc = acc0 + acc1;
#pragma unroll
    for (int o = 16; o; o >>= 1)
        acc += __shfl_xor_sync(0xFFFFFFFFu, acc, o);
    if (lane == 0) out[row] = acc + bb;
}

__global__ void __launch_bounds__(256, 2) fused_kernel(
    const float* __restrict__ states,  // (B, T, H)
    const float* __restrict__ ctx,     // (B, H)
    const float* __restrict__ W,       // (H, H)
    const float* __restrict__ bias,    // (1,)
    float* __restrict__ out)           // (B*T,)
{
    __shared__ float red[4][8][9];     // v-phase cross-warp reduce

    const int tid  = threadIdx.x;
    const int lane = tid & 31;
    const int warp = tid >> 5;
    const int wg   = blockIdx.x * 8 + warp;
    const bool writer = blockIdx.x < V_WRITERS;

    float4 xa[8], xb[8];

    if (writer) {
        // ── v-phase (R15 form): 4 W rows front-batched, ONE ctx pass ──
        float4 w4[4];
#pragma unroll
        for (int r = 0; r < 4; r++)
            w4[r] = __ldg(reinterpret_cast<const float4*>(
                        W + (size_t)(blockIdx.x * 4 + r) * H) + tid);

        float acc[4][B];
#pragma unroll
        for (int b = 0; b < B; b++) {
            const float4 c = __ldg(reinterpret_cast<const float4*>(ctx + b * H) + tid);
#pragma unroll
            for (int r = 0; r < 4; r++)
                acc[r][b] = w4[r].x * c.x + w4[r].y * c.y + w4[r].z * c.z + w4[r].w * c.w;
        }
#pragma unroll
        for (int r = 0; r < 4; r++)
#pragma unroll
            for (int b = 0; b < B; b++) {
#pragma unroll
                for (int o = 16; o; o >>= 1)
                    acc[r][b] += __shfl_xor_sync(0xFFFFFFFFu, acc[r][b], o);
            }
        if (lane == 0) {
#pragma unroll
            for (int r = 0; r < 4; r++)
#pragma unroll
                for (int b = 0; b < B; b++) red[r][warp][b] = acc[r][b];
        }
        __syncthreads();
        if (tid < 4 * B) {
            const int r = tid >> 3, b = tid & 7;
            float s = 0.0f;
#pragma unroll
            for (int wi = 0; wi < 8; wi++) s += red[r][wi][b];
            g_v[b * H + blockIdx.x * 4 + r] = s;
        }
        __syncthreads();
        if (tid == 0) {
            __threadfence();              // publish g_v device-wide
            atomicAdd(&g_cnt, 1);
        }
    } else {
        // Non-writers (40 blocks): pre-issue first states row — DRAM stays
        // busy during the v-phase. No register-lifetime overlap with v-phase.
        load_row(xa, states, wg, lane);
    }

    const float bb = bias[0];

    // ── spin barrier: all 256 writer blocks done; self-reset for replay ──
    if (tid == 0) {
        while (ld_acquire(&g_cnt) < V_WRITERS) __nanosleep(32);
        const int old = atomicAdd(&g_passed, 1);
        if (old == GRID - 1) {
            atomicExch(&g_cnt, 0);
            atomicExch(&g_passed, 0);
        }
    }
    __syncthreads();

    // Writers load their first row only now (keeps v-phase regs dead here).
    if (writer) load_row(xa, states, wg, lane);

    // ── engine (R10, verbatim): register ping-pong, ~14 rows per warp ──
    int ra = wg;
    int rb = ra + NWARPS;
    for (;;) {
        if (rb < NROWS) load_row(xb, states, rb, lane);   // prefetch next
        dot_store(xa, ra, lane, bb, out);                 // consume current
        if (rb >= NROWS) break;

        ra = rb + NWARPS;
        if (ra < NROWS) load_row(xa, states, ra, lane);
        dot_store(xb, rb, lane, bb, out);
        if (ra >= NROWS) break;

        rb = ra + NWARPS;
    }
}

extern "C" void kernel_launch(void* const* d_in, const int* in_sizes, int n_in,
                              void* d_out, int out_size)
{
    const float* states = (const float*)d_in[0];   // (B, T, H)
    const float* ctx    = (const float*)d_in[1];   // (B, H)
    const float* W      = (const float*)d_in[2];   // (1, H, H)
    const float* bias   = (const float*)d_in[3];   // (1,)

    fused_kernel<<<GRID, 256>>>(states, ctx, W, bias, (float*)d_out);
}

// round 17
// speedup vs baseline: 1.2338x; 1.2338x over previous
#include <cuda_runtime.h>
#include <cstdint>

#define H 1024
#define B 8
#define T 4096
#define NROWS (B * T)

#define GRID      296              // 148 SMs x 2 blocks — all co-resident
#define NWARPS    (GRID * 8)       // 2368 warps, 13-14 rows each
#define V_WRITERS 256              // blocks 0..255 compute 4 v-rows each
#define STAGES    3
#define ROW_BYTES (H * 4)          // 4096
#define SMEM_DYN  (8 * STAGES * H * 4)   // 96 KB: per-warp 3-stage rings

__device__ float g_v[B * H];
__device__ int   g_cnt;            // writer blocks done (self-resetting)
__device__ int   g_passed;         // blocks past spin (self-resetting)

__device__ __forceinline__ int ld_acquire(const int* p) {
    int v;
    asm volatile("ld.global.acquire.gpu.b32 %0, [%1];" : "=r"(v) : "l"(p) : "memory");
    return v;
}
__device__ __forceinline__ uint32_t smem_u32(const void* p) {
    uint32_t a;
    asm("{ .reg .u64 t; cvta.to.shared.u64 t, %1; cvt.u32.u64 %0, t; }" : "=r"(a) : "l"(p));
    return a;
}
__device__ __forceinline__ void mbar_init(uint32_t mbar, uint32_t cnt) {
    asm volatile("mbarrier.init.shared.b64 [%0], %1;" :: "r"(mbar), "r"(cnt) : "memory");
}
__device__ __forceinline__ void mbar_expect_tx(uint32_t mbar, uint32_t bytes) {
    asm volatile("mbarrier.arrive.expect_tx.shared.b64 _, [%0], %1;" :: "r"(mbar), "r"(bytes) : "memory");
}
__device__ __forceinline__ void bulk_g2s(uint32_t dst, const void* src, uint32_t bytes, uint32_t mbar) {
    asm volatile("cp.async.bulk.shared::cluster.global.mbarrier::complete_tx::bytes [%0], [%1], %2, [%3];"
                 :: "r"(dst), "l"(src), "r"(bytes), "r"(mbar) : "memory");
}
__device__ __forceinline__ void mbar_wait(uint32_t mbar, uint32_t parity) {
    asm volatile(
        "{\n\t"
        ".reg .pred P;\n\t"
        "W_%=:\n\t"
        "mbarrier.try_wait.parity.acquire.cta.shared::cta.b64 P, [%0], %1, 0x989680;\n\t"
        "@P bra D_%=;\n\t"
        "bra W_%=;\n\t"
        "D_%=:\n\t"
        "}" :: "r"(mbar), "r"(parity) : "memory");
}

__global__ void __launch_bounds__(256) fused_kernel(
    const float* __restrict__ states,  // (B, T, H)
    const float* __restrict__ ctx,     // (B, H)
    const float* __restrict__ W,       // (H, H)
    const float* __restrict__ bias,    // (1,)
    float* __restrict__ out)           // (B*T,)
{
    extern __shared__ float ring_all[];                 // [8 warps][3 stages][H]
    __shared__ float red[4][8][9];                      // v-phase reduce
    __shared__ alignas(8) unsigned long long mbars[8][STAGES];

    const int tid  = threadIdx.x;
    const int lane = tid & 31;
    const int warp = tid >> 5;
    const int wg   = blockIdx.x * 8 + warp;

    float* ring = ring_all + warp * (STAGES * H);
    const uint32_t mb0 = smem_u32(&mbars[warp][0]);

    // Per-warp mbarrier init + prologue copies (issued BEFORE the v-phase:
    // no registers consumed, DRAM busy from t=0).
    if (lane == 0) {
#pragma unroll
        for (int s = 0; s < STAGES; s++) mbar_init(mb0 + 8 * s, 1);
        asm volatile("fence.proxy.async.shared::cta;" ::: "memory");
#pragma unroll
        for (int s = 0; s < STAGES; s++) {
            const int row = wg + s * NWARPS;
            if (row < NROWS) {
                mbar_expect_tx(mb0 + 8 * s, ROW_BYTES);
                bulk_g2s(smem_u32(ring + s * H), states + (size_t)row * H,
                         ROW_BYTES, mb0 + 8 * s);
            }
        }
    }

    // ── v-phase: blocks 0..255, 4 W rows front-batched, ONE ctx pass ──
    if (blockIdx.x < V_WRITERS) {
        float4 w4[4];
#pragma unroll
        for (int r = 0; r < 4; r++)
            w4[r] = __ldg(reinterpret_cast<const float4*>(
                        W + (size_t)(blockIdx.x * 4 + r) * H) + tid);

        float acc[4][B];
#pragma unroll
        for (int b = 0; b < B; b++) {
            const float4 c = __ldg(reinterpret_cast<const float4*>(ctx + b * H) + tid);
#pragma unroll
            for (int r = 0; r < 4; r++)
                acc[r][b] = w4[r].x * c.x + w4[r].y * c.y + w4[r].z * c.z + w4[r].w * c.w;
        }
#pragma unroll
        for (int r = 0; r < 4; r++)
#pragma unroll
            for (int b = 0; b < B; b++) {
#pragma unroll
                for (int o = 16; o; o >>= 1)
                    acc[r][b] += __shfl_xor_sync(0xFFFFFFFFu, acc[r][b], o);
            }
        if (lane == 0) {
#pragma unroll
            for (int r = 0; r < 4; r++)
#pragma unroll
                for (int b = 0; b < B; b++) red[r][warp][b] = acc[r][b];
        }
        __syncthreads();
        if (tid < 4 * B) {
            const int r = tid >> 3, b = tid & 7;
            float s = 0.0f;
#pragma unroll
            for (int wi = 0; wi < 8; wi++) s += red[r][wi][b];
            g_v[b * H + blockIdx.x * 4 + r] = s;
        }
        __syncthreads();
        if (tid == 0) { __threadfence(); atomicAdd(&g_cnt, 1); }
    }

    // ── spin barrier: all writers done; self-reset for graph replay ──
    if (tid == 0) {
        while (ld_acquire(&g_cnt) < V_WRITERS) __nanosleep(32);
        const int old = atomicAdd(&g_passed, 1);
        if (old == GRID - 1) { atomicExch(&g_cnt, 0); atomicExch(&g_passed, 0); }
    }
    __syncthreads();

    const float bb = bias[0];

    // ── engine: per-warp 3-deep bulk-copy ring, no block sync ──
    int stage = 0;
    uint32_t ph = 0;   // per-stage parity bits
    for (int row = wg; row < NROWS; row += NWARPS) {
        mbar_wait(mb0 + 8 * stage, (ph >> stage) & 1);
        ph ^= (1u << stage);

        const float4* x4 = reinterpret_cast<const float4*>(ring + stage * H);
        const float4* v4 = reinterpret_cast<const float4*>(g_v + ((row >> 12) << 10));

        float acc0 = 0.0f, acc1 = 0.0f;
#pragma unroll
        for (int k = 0; k < 8; k += 2) {
            const float4 x0 = x4[lane + 32 * k];
            const float4 x1 = x4[lane + 32 * (k + 1)];
            const float4 w0 = __ldg(v4 + lane + 32 * k);
            const float4 w1 = __ldg(v4 + lane + 32 * (k + 1));
            acc0 += x0.x * w0.x + x0.y * w0.y + x0.z * w0.z + x0.w * w0.w;
            acc1 += x1.x * w1.x + x1.y * w1.y + x1.z * w1.z + x1.w * w1.w;
        }
        float acc = acc0 + acc1;
#pragma unroll
        for (int o = 16; o; o >>= 1)
            acc += __shfl_xor_sync(0xFFFFFFFFu, acc, o);
        if (lane == 0) out[row] = acc + bb;

        // Refill this stage (all lanes' smem reads are done: the shfl.sync
        // chain above forces warp convergence after the LDS consumes).
        const int nr = row + STAGES * NWARPS;
        if (lane == 0 && nr < NROWS) {
            mbar_expect_tx(mb0 + 8 * stage, ROW_BYTES);
            bulk_g2s(smem_u32(ring + stage * H), states + (size_t)nr * H,
                     ROW_BYTES, mb0 + 8 * stage);
        }
        if (++stage == STAGES) stage = 0;
    }
}

extern "C" void kernel_launch(void* const* d_in, const int* in_sizes, int n_in,
                              void* d_out, int out_size)
{
    const float* states = (const float*)d_in[0];   // (B, T, H)
    const float* ctx    = (const float*)d_in[1];   // (B, H)
    const float* W      = (const float*)d_in[2];   // (1, H, H)
    const float* bias   = (const float*)d_in[3];   // (1,)

    cudaFuncSetAttribute(fused_kernel,
                         cudaFuncAttributeMaxDynamicSharedMemorySize, SMEM_DYN);
    fused_kernel<<<GRID, 256, SMEM_DYN>>>(states, ctx, W, bias, (float*)d_out);
}